// round 4
// baseline (speedup 1.0000x reference)
#include <cuda_runtime.h>
#include <math.h>

#define N 8192
#define D 512
#define TM 64
#define TN 64
#define BK 64
#define TNP (TN + 1)
#define KTOP 5

// Scratch (no cudaMalloc allowed)
static __device__ float g_xn[(size_t)N * D];     // 16 MB normalized rows
static __device__ float g_logrho[N];             // per-row log(mean_rho + eps)

// ---------------------------------------------------------------------------
// Kernel 1: row-normalize. One block (128 threads) per row, float4 IO.
// ---------------------------------------------------------------------------
__global__ void knorm(const float* __restrict__ x, float* __restrict__ xn) {
    int row = blockIdx.x;
    int t = threadIdx.x;  // 0..127, 128 * float4 = 512 floats
    const float4* xr = (const float4*)(x + (size_t)row * D);
    float4 v = xr[t];
    float s = v.x * v.x + v.y * v.y + v.z * v.z + v.w * v.w;
    #pragma unroll
    for (int o = 16; o; o >>= 1) s += __shfl_xor_sync(0xffffffffu, s, o);
    __shared__ float ws[4];
    if ((t & 31) == 0) ws[t >> 5] = s;
    __syncthreads();
    float tot = ws[0] + ws[1] + ws[2] + ws[3];
    float inv = rsqrtf(tot);
    float4 o4 = make_float4(v.x * inv, v.y * inv, v.z * inv, v.w * inv);
    ((float4*)(xn + (size_t)row * D))[t] = o4;
}

// ---------------------------------------------------------------------------
// Kernel 2: fused GEMM (Xn Xn^T) + per-row top-5 of dots (diag excluded).
// Grid: N/TM = 128 blocks, 256 threads. A-panel (64 rows x 512) resident in
// SMEM; stream B tiles. Each thread computes a 4x4 micro-tile; after each
// 64x64 C tile, 256 threads scan it (4 threads/row x 16 cols) keeping private
// top-5 registers; final per-row merge of the 4 partials.
// ---------------------------------------------------------------------------
__global__ void gemm_topk(const float* __restrict__ xn, float* __restrict__ logrho) {
    extern __shared__ float sm[];
    float* As = sm;                 // [D][TM]   : As[k*TM + r]   (128 KB)
    float* Bs = As + D * TM;        // [BK][TN]  : Bs[k*TN + c]   (16 KB)
    float* Cs = Bs + BK * TN;       // [TM][TNP]                  (16.25 KB)

    const int tid = threadIdx.x;
    const int brow = blockIdx.x * TM;

    // ---- Load resident A panel: 64 rows x 512 K, transposed to As[k][r] ----
    {
        int r = tid & 63;
        int kq = (tid >> 6) * 4;           // 0,4,8,12
        const float* src = xn + (size_t)(brow + r) * D;
        #pragma unroll
        for (int rep = 0; rep < 32; rep++) {
            int k = kq + rep * 16;
            float4 v = *(const float4*)(src + k);
            As[(k + 0) * TM + r] = v.x;
            As[(k + 1) * TM + r] = v.y;
            As[(k + 2) * TM + r] = v.z;
            As[(k + 3) * TM + r] = v.w;
        }
    }
    __syncthreads();

    // private partial top-5 (ascending: t0 = smallest of the kept 5)
    float t0 = -2.f, t1 = -2.f, t2 = -2.f, t3 = -2.f, t4 = -2.f;

    const int tr = (tid >> 4) * 4;  // micro-tile row offset (0..60)
    const int tc = (tid & 15) * 4;  // micro-tile col offset (0..60)
    const int rr = tid & 63;        // scan: row
    const int part = tid >> 6;      // scan: which 16-col slice
    const int rg = brow + rr;

    for (int ct = 0; ct < N / TN; ct++) {
        float acc[4][4];
        #pragma unroll
        for (int i = 0; i < 4; i++)
            #pragma unroll
            for (int j = 0; j < 4; j++) acc[i][j] = 0.f;

        for (int kb = 0; kb < D; kb += BK) {
            // load B tile: cols ct*64..+63, k = kb..kb+63 -> Bs[k][c]
            {
                int c = tid & 63;
                int kq = (tid >> 6) * 4;
                const float* src = xn + (size_t)(ct * TN + c) * D + kb;
                #pragma unroll
                for (int rep = 0; rep < 4; rep++) {
                    int k = kq + rep * 16;
                    float4 v = *(const float4*)(src + k);
                    Bs[(k + 0) * TN + c] = v.x;
                    Bs[(k + 1) * TN + c] = v.y;
                    Bs[(k + 2) * TN + c] = v.z;
                    Bs[(k + 3) * TN + c] = v.w;
                }
            }
            __syncthreads();

            #pragma unroll 8
            for (int k = 0; k < BK; k++) {
                float4 a = *(const float4*)&As[(kb + k) * TM + tr];
                float4 b = *(const float4*)&Bs[k * TN + tc];
                float av[4] = {a.x, a.y, a.z, a.w};
                float bv[4] = {b.x, b.y, b.z, b.w};
                #pragma unroll
                for (int i = 0; i < 4; i++)
                    #pragma unroll
                    for (int j = 0; j < 4; j++)
                        acc[i][j] = fmaf(av[i], bv[j], acc[i][j]);
            }
            __syncthreads();
        }

        // stash C tile to SMEM for the per-row scan
        #pragma unroll
        for (int i = 0; i < 4; i++)
            #pragma unroll
            for (int j = 0; j < 4; j++)
                Cs[(tr + i) * TNP + (tc + j)] = acc[i][j];
        __syncthreads();

        // scan 16 cols per thread, update private top-5
        #pragma unroll 4
        for (int cc = 0; cc < 16; cc++) {
            int c = part * 16 + cc;
            float v = Cs[rr * TNP + c];
            int cg = ct * TN + c;
            if (cg != rg && v > t0) {
                t0 = v;
                if (t0 > t1) { float tmp = t0; t0 = t1; t1 = tmp;
                  if (t1 > t2) { tmp = t1; t1 = t2; t2 = tmp;
                    if (t2 > t3) { tmp = t2; t2 = t3; t3 = tmp;
                      if (t3 > t4) { tmp = t3; t3 = t4; t4 = tmp; } } } }
            }
        }
        __syncthreads();  // protect Cs before next tile's writes
    }

    // ---- merge the 4 partial top-5 lists per row ----
    Cs[rr * TNP + part * 5 + 0] = t0;
    Cs[rr * TNP + part * 5 + 1] = t1;
    Cs[rr * TNP + part * 5 + 2] = t2;
    Cs[rr * TNP + part * 5 + 3] = t3;
    Cs[rr * TNP + part * 5 + 4] = t4;
    __syncthreads();

    if (tid < TM) {
        float vals[20];
        #pragma unroll
        for (int i = 0; i < 20; i++) vals[i] = Cs[tid * TNP + i];
        float sum = 0.f;
        #pragma unroll
        for (int s = 0; s < KTOP; s++) {
            int bi = 0;
            float bv = vals[0];
            #pragma unroll
            for (int i = 1; i < 20; i++)
                if (vals[i] > bv) { bv = vals[i]; bi = i; }
            vals[bi] = -9.f;
            sum += sqrtf(fmaxf(2.f - 2.f * bv, 0.f));
        }
        float mean_rho = sum * (1.f / KTOP);
        logrho[brow + tid] = logf(mean_rho + 1e-8f);
    }
}

// ---------------------------------------------------------------------------
// Kernel 3: final reduction: out = -mean(logrho)
// ---------------------------------------------------------------------------
__global__ void kred(const float* __restrict__ lr, float* __restrict__ out) {
    int t = threadIdx.x;  // 256 threads, single block
    float s = 0.f;
    for (int i = t; i < N; i += 256) s += lr[i];
    #pragma unroll
    for (int o = 16; o; o >>= 1) s += __shfl_xor_sync(0xffffffffu, s, o);
    __shared__ float ws[8];
    if ((t & 31) == 0) ws[t >> 5] = s;
    __syncthreads();
    if (t == 0) {
        float tot = 0.f;
        #pragma unroll
        for (int i = 0; i < 8; i++) tot += ws[i];
        out[0] = -tot / (float)N;
    }
}

// ---------------------------------------------------------------------------
extern "C" void kernel_launch(void* const* d_in, const int* in_sizes, int n_in,
                              void* d_out, int out_size) {
    (void)in_sizes; (void)n_in; (void)out_size;
    const float* x = (const float*)d_in[0];
    float* out = (float*)d_out;

    float* xn;     cudaGetSymbolAddress((void**)&xn, g_xn);
    float* lrho;   cudaGetSymbolAddress((void**)&lrho, g_logrho);

    const size_t smem = (size_t)(D * TM + BK * TN + TM * TNP) * sizeof(float);
    cudaFuncSetAttribute(gemm_topk, cudaFuncAttributeMaxDynamicSharedMemorySize, (int)smem);

    knorm<<<N, 128>>>(x, xn);
    gemm_topk<<<N / TM, 256, smem>>>(xn, lrho);
    kred<<<1, 256>>>(lrho, out);
}

// round 8
// speedup vs baseline: 10.2993x; 10.2993x over previous
#include <cuda_runtime.h>
#include <cuda_bf16.h>
#include <math.h>
#include <stdint.h>

#define N 8192
#define D 512
#define TM 128           // M rows per CTA
#define TNT 128          // cols per column tile
#define KC 64            // K chunk per B SMEM tile
#define KTOP 5
#define NTILES ((N / 2) / TNT)   // 32 column tiles per CTA (half the matrix)

// Scratch (no cudaMalloc allowed)
static __device__ __nv_bfloat16 g_xnb[(size_t)N * D];   // 8 MB normalized rows, bf16
static __device__ float g_top[(size_t)N * 10];          // per-row top5 from each half
static __device__ float g_logrho[N];

// SMEM: A panel 128 KB resident + 2x 16 KB B buffers (merge area reuses A)
#define SA_BYTES (128 * 1024)
#define SB_BYTES (16 * 1024)
#define SMEM_TOTAL (SA_BYTES + 2 * SB_BYTES)

// ---- PTX helpers ------------------------------------------------------------
__device__ __forceinline__ uint32_t smem_u32(const void* p) {
    uint32_t a;
    asm("{ .reg .u64 t; cvta.to.shared.u64 t, %1; cvt.u32.u64 %0, t; }" : "=r"(a) : "l"(p));
    return a;
}
__device__ __forceinline__ void ldsm_x4(uint32_t* r, uint32_t addr) {
    asm volatile("ldmatrix.sync.aligned.m8n8.x4.shared.b16 {%0,%1,%2,%3}, [%4];"
                 : "=r"(r[0]), "=r"(r[1]), "=r"(r[2]), "=r"(r[3]) : "r"(addr));
}
__device__ __forceinline__ void mma_bf16(float* d, const uint32_t* a,
                                         uint32_t b0, uint32_t b1) {
    asm volatile(
        "mma.sync.aligned.m16n8k16.row.col.f32.bf16.bf16.f32 "
        "{%0,%1,%2,%3}, {%4,%5,%6,%7}, {%8,%9}, {%0,%1,%2,%3};"
        : "+f"(d[0]), "+f"(d[1]), "+f"(d[2]), "+f"(d[3])
        : "r"(a[0]), "r"(a[1]), "r"(a[2]), "r"(a[3]), "r"(b0), "r"(b1));
}
__device__ __forceinline__ void cp16(uint32_t dst, const void* src) {
    asm volatile("cp.async.cg.shared.global [%0], [%1], 16;" :: "r"(dst), "l"(src));
}
__device__ __forceinline__ void cp_commit() {
    asm volatile("cp.async.commit_group;" ::: "memory");
}
__device__ __forceinline__ void cp_wait1() {
    asm volatile("cp.async.wait_group 1;" ::: "memory");
}
__device__ __forceinline__ void cp_wait0() {
    asm volatile("cp.async.wait_group 0;" ::: "memory");
}

// ---------------------------------------------------------------------------
// Kernel 1: row-normalize + cast to bf16. One block (128 threads) per row.
// ---------------------------------------------------------------------------
__global__ void knorm(const float* __restrict__ x, __nv_bfloat16* __restrict__ xnb) {
    int row = blockIdx.x;
    int t = threadIdx.x;
    float4 v = ((const float4*)(x + (size_t)row * D))[t];
    float s = v.x * v.x + v.y * v.y + v.z * v.z + v.w * v.w;
    #pragma unroll
    for (int o = 16; o; o >>= 1) s += __shfl_xor_sync(0xffffffffu, s, o);
    __shared__ float ws[4];
    if ((t & 31) == 0) ws[t >> 5] = s;
    __syncthreads();
    float inv = rsqrtf(ws[0] + ws[1] + ws[2] + ws[3]);
    __nv_bfloat162 p0 = __floats2bfloat162_rn(v.x * inv, v.y * inv);
    __nv_bfloat162 p1 = __floats2bfloat162_rn(v.z * inv, v.w * inv);
    uint2 o2;
    o2.x = *(uint32_t*)&p0;
    o2.y = *(uint32_t*)&p1;
    ((uint2*)(xnb + (size_t)row * D))[t] = o2;
}

// ---------------------------------------------------------------------------
// Kernel 2: mma.sync bf16 GEMM (Xn Xn^T) + fused per-row top-5 in registers.
// Grid (64, 2): 64 M-tiles x 2 column halves. 256 threads = 8 warps (4M x 2N).
// Warp tile: 32 rows x 64 cols = 2x8 m16n8k16 fragments, K accumulated fully
// per column tile, then scanned directly from accumulator registers.
// ---------------------------------------------------------------------------
__global__ void __launch_bounds__(256, 1)
gemm_topk(const __nv_bfloat16* __restrict__ xnb, float* __restrict__ gtop) {
    extern __shared__ char smem[];
    const uint32_t sb = smem_u32(smem);
    const int tid = threadIdx.x;
    const int wid = tid >> 5, lane = tid & 31;
    const int wm = wid & 3, wn = wid >> 2;
    const int brow = blockIdx.x * TM;
    const int colbase = blockIdx.y * (N / 2);

    const int q = lane >> 3;         // ldmatrix quadrant
    const int lr = lane & 7;         // ldmatrix row-within-quadrant
    const uint32_t swz = (uint32_t)lr << 4;  // 16B-chunk XOR swizzle

    // ---- Load resident A panel: 128 rows x 512 bf16, swizzled ----
    #pragma unroll 8
    for (int it = 0; it < 32; it++) {
        int idx = tid + it * 256;          // 0..8191 16B chunks
        int r = idx >> 6, c16 = idx & 63;
        uint32_t off = (uint32_t)r * 1024 + (uint32_t)c16 * 16;
        uint32_t sw = off ^ ((uint32_t)(r & 7) << 4);
        *(uint4*)(smem + sw) = *(const uint4*)(xnb + (size_t)(brow + r) * D + c16 * 8);
    }

    // ldmatrix base offsets (additive parts; XOR applied at use)
    uint32_t aoff[2], boff[4];
    #pragma unroll
    for (int mt = 0; mt < 2; mt++) {
        int arow = wm * 32 + mt * 16 + (q & 1) * 8 + lr;
        aoff[mt] = (uint32_t)arow * 1024 + (uint32_t)(q >> 1) * 16;
    }
    #pragma unroll
    for (int np = 0; np < 4; np++) {
        int bn = wn * 64 + np * 16 + (q & 1) * 8 + lr;
        boff[np] = (uint32_t)bn * 128 + (uint32_t)(q >> 1) * 16;
    }

    // private top-5 per row-slot (ascending; [0] = smallest kept)
    float tp[4][5];
    #pragma unroll
    for (int s = 0; s < 4; s++)
        #pragma unroll
        for (int i = 0; i < 5; i++) tp[s][i] = -2.f;

    int rowg[4];
    #pragma unroll
    for (int mt = 0; mt < 2; mt++)
        #pragma unroll
        for (int half = 0; half < 2; half++)
            rowg[mt * 2 + half] = brow + wm * 32 + mt * 16 + half * 8 + (lane >> 2);

    // B prefetch lambda-ish: each thread copies 4x16B of a [128 x 64] chunk
    const int bn0 = (tid * 4) >> 3;          // base handled via idx math below

    // preload tile0 chunk0 into buf0
    {
        const int col0 = colbase;
        #pragma unroll
        for (int it = 0; it < 4; it++) {
            int idx = tid + it * 256;        // 0..1023 16B chunks
            int n = idx >> 3, c16 = idx & 7;
            uint32_t off = (uint32_t)n * 128 + (uint32_t)c16 * 16;
            uint32_t sw = off ^ ((uint32_t)(n & 7) << 4);
            cp16(sb + SA_BYTES + sw, xnb + (size_t)(col0 + n) * D + c16 * 8);
        }
        cp_commit();
    }
    (void)bn0;

    for (int ct = 0; ct < NTILES; ct++) {
        const int col0 = colbase + ct * TNT;

        float acc[2][8][4];
        #pragma unroll
        for (int mt = 0; mt < 2; mt++)
            #pragma unroll
            for (int nt = 0; nt < 8; nt++)
                #pragma unroll
                for (int j = 0; j < 4; j++) acc[mt][nt][j] = 0.f;

        #pragma unroll
        for (int kb = 0; kb < D / KC; kb++) {
            // prefetch next chunk (or next tile's chunk0) into the other buffer
            if (kb < 7) {
                uint32_t dstb = sb + SA_BYTES + ((kb + 1) & 1) * SB_BYTES;
                #pragma unroll
                for (int it = 0; it < 4; it++) {
                    int idx = tid + it * 256;
                    int n = idx >> 3, c16 = idx & 7;
                    uint32_t off = (uint32_t)n * 128 + (uint32_t)c16 * 16;
                    uint32_t sw = off ^ ((uint32_t)(n & 7) << 4);
                    cp16(dstb + sw, xnb + (size_t)(col0 + n) * D + (kb + 1) * KC + c16 * 8);
                }
                cp_commit();
                cp_wait1();
            } else if (ct + 1 < NTILES) {
                uint32_t dstb = sb + SA_BYTES;  // buf0
                int ncol0 = colbase + (ct + 1) * TNT;
                #pragma unroll
                for (int it = 0; it < 4; it++) {
                    int idx = tid + it * 256;
                    int n = idx >> 3, c16 = idx & 7;
                    uint32_t off = (uint32_t)n * 128 + (uint32_t)c16 * 16;
                    uint32_t sw = off ^ ((uint32_t)(n & 7) << 4);
                    cp16(dstb + sw, xnb + (size_t)(ncol0 + n) * D + c16 * 8);
                }
                cp_commit();
                cp_wait1();
            } else {
                cp_wait0();
            }
            __syncthreads();

            const uint32_t bbase = sb + SA_BYTES + (kb & 1) * SB_BYTES;

            #pragma unroll
            for (int k16 = 0; k16 < 4; k16++) {
                uint32_t a[2][4], b[4][4];
                #pragma unroll
                for (int mt = 0; mt < 2; mt++)
                    ldsm_x4(a[mt], sb + ((aoff[mt] + kb * 128 + k16 * 32) ^ swz));
                #pragma unroll
                for (int np = 0; np < 4; np++)
                    ldsm_x4(b[np], bbase + ((boff[np] + k16 * 32) ^ swz));
                #pragma unroll
                for (int mt = 0; mt < 2; mt++)
                    #pragma unroll
                    for (int nt = 0; nt < 8; nt++) {
                        const int np = nt >> 1, w = nt & 1;
                        mma_bf16(acc[mt][nt], a[mt], b[np][w], b[np][w + 2]);
                    }
            }
            __syncthreads();  // all reads of this buffer done before it is refilled
        }

        // ---- scan accumulators into private top-5 (register-only) ----
        #pragma unroll
        for (int mt = 0; mt < 2; mt++)
            #pragma unroll
            for (int half = 0; half < 2; half++) {
                const int s = mt * 2 + half;
                const int rg = rowg[s];
                #pragma unroll
                for (int nt = 0; nt < 8; nt++)
                    #pragma unroll
                    for (int j = 0; j < 2; j++) {
                        float v = acc[mt][nt][half * 2 + j];
                        int cg = col0 + wn * 64 + nt * 8 + 2 * (lane & 3) + j;
                        if (cg != rg && v > tp[s][0]) {
                            tp[s][0] = v;
                            #pragma unroll
                            for (int i = 0; i < 4; i++) {
                                if (tp[s][i] > tp[s][i + 1]) {
                                    float tm = tp[s][i];
                                    tp[s][i] = tp[s][i + 1];
                                    tp[s][i + 1] = tm;
                                }
                            }
                        }
                    }
            }
    }

    // ---- merge 8 partial lists per row via SMEM (reuse A area) ----
    __syncthreads();
    float* mrg = (float*)smem;  // [128][40]
    #pragma unroll
    for (int mt = 0; mt < 2; mt++)
        #pragma unroll
        for (int half = 0; half < 2; half++) {
            const int s = mt * 2 + half;
            int rl = wm * 32 + mt * 16 + half * 8 + (lane >> 2);
            int w = wn * 4 + (lane & 3);
            #pragma unroll
            for (int i = 0; i < 5; i++)
                mrg[rl * 40 + w * 5 + i] = tp[s][i];
        }
    __syncthreads();

    if (tid < 128) {
        float t0 = -2.f, t1 = -2.f, t2 = -2.f, t3 = -2.f, t4 = -2.f;
        #pragma unroll 8
        for (int i = 0; i < 40; i++) {
            float v = mrg[tid * 40 + i];
            if (v > t0) {
                t0 = v;
                if (t0 > t1) { float tm = t0; t0 = t1; t1 = tm;
                  if (t1 > t2) { tm = t1; t1 = t2; t2 = tm;
                    if (t2 > t3) { tm = t2; t2 = t3; t3 = tm;
                      if (t3 > t4) { tm = t3; t3 = t4; t4 = tm; } } } }
            }
        }
        float* dst = gtop + (size_t)(brow + tid) * 10 + blockIdx.y * 5;
        dst[0] = t0; dst[1] = t1; dst[2] = t2; dst[3] = t3; dst[4] = t4;
    }
}

// ---------------------------------------------------------------------------
// Kernel 3: merge the two halves' top-5 lists, compute log(mean_rho + eps).
// ---------------------------------------------------------------------------
__global__ void kfinal(const float* __restrict__ gtop, float* __restrict__ lr) {
    int row = blockIdx.x * 256 + threadIdx.x;
    float v[10];
    #pragma unroll
    for (int i = 0; i < 10; i++) v[i] = gtop[(size_t)row * 10 + i];
    float sum = 0.f;
    #pragma unroll
    for (int s = 0; s < KTOP; s++) {
        int bi = 0; float bv = v[0];
        #pragma unroll
        for (int i = 1; i < 10; i++)
            if (v[i] > bv) { bv = v[i]; bi = i; }
        v[bi] = -9.f;
        sum += sqrtf(fmaxf(2.f - 2.f * bv, 0.f));
    }
    lr[row] = logf(sum * (1.f / KTOP) + 1e-8f);
}

// ---------------------------------------------------------------------------
// Kernel 4: out = -mean(logrho)
// ---------------------------------------------------------------------------
__global__ void kred(const float* __restrict__ lr, float* __restrict__ out) {
    int t = threadIdx.x;
    float s = 0.f;
    for (int i = t; i < N; i += 256) s += lr[i];
    #pragma unroll
    for (int o = 16; o; o >>= 1) s += __shfl_xor_sync(0xffffffffu, s, o);
    __shared__ float ws[8];
    if ((t & 31) == 0) ws[t >> 5] = s;
    __syncthreads();
    if (t == 0) {
        float tot = 0.f;
        #pragma unroll
        for (int i = 0; i < 8; i++) tot += ws[i];
        out[0] = -tot / (float)N;
    }
}

// ---------------------------------------------------------------------------
extern "C" void kernel_launch(void* const* d_in, const int* in_sizes, int n_in,
                              void* d_out, int out_size) {
    (void)in_sizes; (void)n_in; (void)out_size;
    const float* x = (const float*)d_in[0];
    float* out = (float*)d_out;

    __nv_bfloat16* xnb; cudaGetSymbolAddress((void**)&xnb, g_xnb);
    float* gtop;        cudaGetSymbolAddress((void**)&gtop, g_top);
    float* lrho;        cudaGetSymbolAddress((void**)&lrho, g_logrho);

    cudaFuncSetAttribute(gemm_topk, cudaFuncAttributeMaxDynamicSharedMemorySize, SMEM_TOTAL);

    knorm<<<N, 128>>>(x, xnb);
    gemm_topk<<<dim3(N / TM, 2), 256, SMEM_TOTAL>>>(xnb, gtop);
    kfinal<<<N / 256, 256>>>(gtop, lrho);
    kred<<<1, 256>>>(lrho, out);
}